// round 6
// baseline (speedup 1.0000x reference)
#include <cuda_runtime.h>
#include <cuda_bf16.h>
#include <cstdint>

#define NTOK  8192
#define INDIM 1024
#define CDIM  512

using bf16 = __nv_bfloat16;

// Packed tile: 128 rows x 32 cols bf16, pitch 80 B; hi (10240 B) then lo. 20480 B.
#define TILE_B  20480
#define TILE_HI 10240

// ---------------------------------------------------------------------------
__device__ __align__(1024) char g_Sp[(size_t)2048 * TILE_B];    // S: [rb 64][kc 32]
__device__ __align__(1024) char g_Wp[3][(size_t)128 * TILE_B];  // W: [rb 4][kc 32]
__device__ __align__(1024) char g_Qp[(size_t)1024 * TILE_B];    // Q: [rb 64][kc 16]
__device__ __align__(1024) char g_Kp[(size_t)1024 * TILE_B];    // K: [rb 64][kc 16]
__device__ __align__(1024) char g_Vtp[(size_t)1024 * TILE_B];   // V^T: [rb 4][kc 256]
__device__ __align__(1024) char g_Pp[(size_t)16384 * TILE_B];   // P: [rb 64][kc 256]
__device__ float g_rowsum[NTOK];

// ---------------------------------------------------------------------------
__device__ __forceinline__ uint32_t su32(const void* p) {
    uint32_t a;
    asm("{ .reg .u64 t; cvta.to.shared.u64 t, %1; cvt.u32.u64 %0, t; }" : "=r"(a) : "l"(p));
    return a;
}
__device__ __forceinline__ void mbar_init(uint32_t m, uint32_t c) {
    asm volatile("mbarrier.init.shared.b64 [%0], %1;" :: "r"(m), "r"(c) : "memory");
}
__device__ __forceinline__ void mbar_expect(uint32_t m, uint32_t bytes) {
    asm volatile("mbarrier.arrive.expect_tx.shared.b64 _, [%0], %1;" :: "r"(m), "r"(bytes) : "memory");
}
__device__ __forceinline__ void mbar_wait(uint32_t m, uint32_t parity) {
    asm volatile(
        "{\n\t.reg .pred P1;\n\t"
        "WL_%=:\n\t"
        "mbarrier.try_wait.parity.acquire.cta.shared::cta.b64 P1, [%0], %1, 0x989680;\n\t"
        "@P1 bra.uni WD_%=;\n\t"
        "bra.uni WL_%=;\n\t"
        "WD_%=:\n\t}"
        :: "r"(m), "r"(parity) : "memory");
}
__device__ __forceinline__ void bulk_g2s(uint32_t sdst, const void* gsrc, uint32_t bytes, uint32_t mbar) {
    asm volatile(
        "cp.async.bulk.shared::cluster.global.mbarrier::complete_tx::bytes [%0], [%1], %2, [%3];"
        :: "r"(sdst), "l"(__cvta_generic_to_global(gsrc)), "r"(bytes), "r"(mbar) : "memory");
}
__device__ __forceinline__ void ldm4(uint32_t& r0, uint32_t& r1, uint32_t& r2, uint32_t& r3, uint32_t a) {
    asm volatile("ldmatrix.sync.aligned.m8n8.x4.shared.b16 {%0,%1,%2,%3}, [%4];"
                 : "=r"(r0), "=r"(r1), "=r"(r2), "=r"(r3) : "r"(a));
}
__device__ __forceinline__ void mma16816(float* c, const uint32_t* a, const uint32_t* b) {
    asm volatile(
        "mma.sync.aligned.m16n8k16.row.col.f32.bf16.bf16.f32 "
        "{%0,%1,%2,%3}, {%4,%5,%6,%7}, {%8,%9}, {%0,%1,%2,%3};"
        : "+f"(c[0]), "+f"(c[1]), "+f"(c[2]), "+f"(c[3])
        : "r"(a[0]), "r"(a[1]), "r"(a[2]), "r"(a[3]), "r"(b[0]), "r"(b[1]));
}
__device__ __forceinline__ void split2(float v, bf16& h, bf16& l) {
    h = __float2bfloat16(v);
    l = __float2bfloat16(v - __bfloat162float(h));
}
__device__ __forceinline__ uint32_t packbf(bf16 a, bf16 b) {
    return ((uint32_t)__bfloat16_as_ushort(b) << 16) | __bfloat16_as_ushort(a);
}

// ---------------------------------------------------------------------------
// SMEM: stage = [A tile 20480][B tile0 20480][B tile1 20480] = 61440 B; 3 stages.
#define STAGE   61440
#define NSTAGE  3
#define SM_RSUM 184320
#define SM_MBAR 184832
#define SM_TOTAL 184864

// Compute one 32-K chunk. Warp tile 64x64: wm in {0,1}, wn in {0..3}.
__device__ __forceinline__ void compute_stage(uint32_t sb, int wm, int wn, int lane,
                                              float acc[4][8][4])
{
    const uint32_t a_off = (lane & 15) * 80 + (lane >> 4) * 16;
    const uint32_t b_off = ((lane & 7) + ((lane >> 4) & 1) * 8) * 80 + ((lane >> 3) & 1) * 16;
    const uint32_t bbase = sb + 20480 + (wn >> 1) * 20480;   // B tile for this warp
    const int bcol = (wn & 1) * 64;                           // local col base in tile
#pragma unroll
    for (int kk = 0; kk < 2; kk++) {
        uint32_t bh[16], bl[16], a[16];
#pragma unroll
        for (int jj = 0; jj < 4; jj++) {
            uint32_t ad = bbase + (bcol + jj * 16) * 80 + kk * 32 + b_off;
            ldm4(bh[jj * 4], bh[jj * 4 + 1], bh[jj * 4 + 2], bh[jj * 4 + 3], ad);
            ldm4(bl[jj * 4], bl[jj * 4 + 1], bl[jj * 4 + 2], bl[jj * 4 + 3], ad + TILE_HI);
        }
#pragma unroll
        for (int i = 0; i < 4; i++) {
            uint32_t ad = sb + (wm * 64 + i * 16) * 80 + kk * 32 + a_off;
            ldm4(a[i * 4], a[i * 4 + 1], a[i * 4 + 2], a[i * 4 + 3], ad);
        }
#pragma unroll
        for (int i = 0; i < 4; i++)
#pragma unroll
            for (int j = 0; j < 8; j++) {
                mma16816(acc[i][j], &a[i * 4], &bh[j * 2]);
                mma16816(acc[i][j], &a[i * 4], &bl[j * 2]);
            }
#pragma unroll
        for (int i = 0; i < 4; i++) {
            uint32_t ad = sb + TILE_HI + (wm * 64 + i * 16) * 80 + kk * 32 + a_off;
            ldm4(a[i * 4], a[i * 4 + 1], a[i * 4 + 2], a[i * 4 + 3], ad);
        }
#pragma unroll
        for (int i = 0; i < 4; i++)
#pragma unroll
            for (int j = 0; j < 8; j++)
                mma16816(acc[i][j], &a[i * 4], &bh[j * 2]);
    }
}

#define ISSUE_CHUNK(kc)                                                                      \
    do {                                                                                     \
        uint32_t s_ = sb + ((kc) % NSTAGE) * STAGE;                                          \
        uint32_t m_ = sb + SM_MBAR + ((kc) % NSTAGE) * 8;                                    \
        mbar_expect(m_, 3 * TILE_B);                                                         \
        bulk_g2s(s_,         Abase + (size_t)(at0 + (kc)) * TILE_B, TILE_B, m_);             \
        bulk_g2s(s_ + 20480, Bbase + (size_t)(bt0 + (kc)) * TILE_B, TILE_B, m_);             \
        bulk_g2s(s_ + 40960, Bbase + (size_t)(bt1 + (kc)) * TILE_B, TILE_B, m_);             \
    } while (0)

#define PACKED_MAINLOOP(AbaseE, at0E, BbaseE, bt0E, bt1E, NCH)                               \
    const char* Abase = (AbaseE); const char* Bbase = (BbaseE);                              \
    const int at0 = (at0E), bt0 = (bt0E), bt1 = (bt1E);                                      \
    if (tid == 0) {                                                                          \
        mbar_init(sb + SM_MBAR, 1); mbar_init(sb + SM_MBAR + 8, 1);                          \
        mbar_init(sb + SM_MBAR + 16, 1);                                                     \
    }                                                                                        \
    __syncthreads();                                                                         \
    if (tid == 0) { ISSUE_CHUNK(0); ISSUE_CHUNK(1); ISSUE_CHUNK(2); }                        \
    for (int kc = 0; kc < (NCH); kc++) {                                                     \
        mbar_wait(sb + SM_MBAR + (kc % NSTAGE) * 8, (uint32_t)((kc / NSTAGE) & 1));          \
        compute_stage(sb + (kc % NSTAGE) * STAGE, wm, wn, lane, acc);                        \
        __syncthreads();                                                                     \
        if (tid == 0 && kc + NSTAGE < (NCH)) ISSUE_CHUNK(kc + NSTAGE);                       \
    }

#define GEMM_PROLOG                                                   \
    extern __shared__ char smem[];                                    \
    const uint32_t sb = su32(smem);                                   \
    const int tid = threadIdx.x;                                      \
    const int lane = tid & 31, warp = tid >> 5;                       \
    const int wm = warp >> 2, wn = warp & 3;                          \
    float acc[4][8][4];                                               \
    _Pragma("unroll") for (int i = 0; i < 4; i++)                     \
    _Pragma("unroll") for (int j = 0; j < 8; j++)                     \
    _Pragma("unroll") for (int k = 0; k < 4; k++) acc[i][j][k] = 0.0f;

// ---------------------------------------------------------------------------
__global__ void zero_rowsum_kernel() {
    int i = blockIdx.x * blockDim.x + threadIdx.x;
    if (i < NTOK) g_rowsum[i] = 0.0f;
}

__global__ __launch_bounds__(256) void split_S_kernel(
    const float* __restrict__ u, const float* __restrict__ z)
{
    int idx = blockIdx.x * 256 + threadIdx.x;
    int row = idx >> 7;
    int c0 = (idx & 127) * 8;
    const float* src = (c0 < 512) ? (u + (size_t)row * 512 + c0)
                                  : (z + (size_t)row * 512 + c0 - 512);
    float4 a = *(const float4*)src;
    float4 b = *(const float4*)(src + 4);
    float x[8] = {a.x, a.y, a.z, a.w, b.x, b.y, b.z, b.w};
    uint32_t hw[4], lw[4];
#pragma unroll
    for (int i = 0; i < 4; i++) {
        bf16 h0, l0, h1, l1;
        split2(x[2 * i], h0, l0); split2(x[2 * i + 1], h1, l1);
        hw[i] = packbf(h0, h1); lw[i] = packbf(l0, l1);
    }
    size_t t = (size_t)(row >> 7) * 32 + (c0 >> 5);
    size_t off = t * TILE_B + (size_t)(row & 127) * 80 + (c0 & 31) * 2;
    *(uint4*)(g_Sp + off)           = make_uint4(hw[0], hw[1], hw[2], hw[3]);
    *(uint4*)(g_Sp + off + TILE_HI) = make_uint4(lw[0], lw[1], lw[2], lw[3]);
}

__global__ __launch_bounds__(256) void split_W_kernel(const float* __restrict__ W, int sel)
{
    int idx = blockIdx.x * 256 + threadIdx.x;
    int row = idx >> 7;
    int c0 = (idx & 127) * 8;
    const float* src = W + (size_t)row * INDIM + c0;
    float4 a = *(const float4*)src;
    float4 b = *(const float4*)(src + 4);
    float x[8] = {a.x, a.y, a.z, a.w, b.x, b.y, b.z, b.w};
    uint32_t hw[4], lw[4];
#pragma unroll
    for (int i = 0; i < 4; i++) {
        bf16 h0, l0, h1, l1;
        split2(x[2 * i], h0, l0); split2(x[2 * i + 1], h1, l1);
        hw[i] = packbf(h0, h1); lw[i] = packbf(l0, l1);
    }
    size_t t = (size_t)(row >> 7) * 32 + (c0 >> 5);
    size_t off = t * TILE_B + (size_t)(row & 127) * 80 + (c0 & 31) * 2;
    *(uint4*)(g_Wp[sel] + off)           = make_uint4(hw[0], hw[1], hw[2], hw[3]);
    *(uint4*)(g_Wp[sel] + off + TILE_HI) = make_uint4(lw[0], lw[1], lw[2], lw[3]);
}

// ---------------------------------------------------------------------------
// Projection: tile 128x256, K=1024. sel: 0->K, 1->V(transposed), 2->Q
__global__ __launch_bounds__(256) void proj_k(const float* __restrict__ bias, int sel)
{
    GEMM_PROLOG;
    const int row0 = blockIdx.y * 128, col0 = blockIdx.x * 256;
    {
        PACKED_MAINLOOP(g_Sp, (row0 >> 7) * 32, g_Wp[sel],
                        (col0 >> 7) * 32, (col0 >> 7) * 32 + 32, INDIM / 32);
    }

    if (sel != 1) {
        char* outp = (sel == 2) ? g_Qp : g_Kp;
#pragma unroll
        for (int i = 0; i < 4; i++)
#pragma unroll
            for (int hb = 0; hb < 2; hb++) {
                int grow = row0 + wm * 64 + i * 16 + (lane >> 2) + hb * 8;
#pragma unroll
                for (int j = 0; j < 8; j++) {
                    int gcol = col0 + wn * 64 + j * 8 + (lane & 3) * 2;
                    float v0 = acc[i][j][hb * 2]     + __ldg(bias + gcol);
                    float v1 = acc[i][j][hb * 2 + 1] + __ldg(bias + gcol + 1);
                    bf16 h0, l0, h1, l1;
                    split2(v0, h0, l0); split2(v1, h1, l1);
                    size_t t = (size_t)(grow >> 7) * 16 + (gcol >> 5);
                    size_t off = t * TILE_B + (size_t)(grow & 127) * 80 + (gcol & 31) * 2;
                    *(uint32_t*)(outp + off)           = packbf(h0, h1);
                    *(uint32_t*)(outp + off + TILE_HI) = packbf(l0, l1);
                }
            }
    } else {
        // V: transpose via smem (reuse mainloop smem; all compute done).
        // hi plane at 0, lo plane at 69632; pitch 272 B; [c 256][tok 128].
        __syncthreads();
#pragma unroll
        for (int i = 0; i < 4; i++)
#pragma unroll
            for (int hb = 0; hb < 2; hb++) {
                int tok = wm * 64 + i * 16 + (lane >> 2) + hb * 8;
#pragma unroll
                for (int j = 0; j < 8; j++) {
                    int cl = wn * 64 + j * 8 + (lane & 3) * 2;
                    float v0 = acc[i][j][hb * 2]     + __ldg(bias + col0 + cl);
                    float v1 = acc[i][j][hb * 2 + 1] + __ldg(bias + col0 + cl + 1);
                    bf16 h0, l0, h1, l1;
                    split2(v0, h0, l0); split2(v1, h1, l1);
                    *(bf16*)(smem + cl * 272 + tok * 2)                 = h0;
                    *(bf16*)(smem + 69632 + cl * 272 + tok * 2)         = l0;
                    *(bf16*)(smem + (cl + 1) * 272 + tok * 2)           = h1;
                    *(bf16*)(smem + 69632 + (cl + 1) * 272 + tok * 2)   = l1;
                }
            }
        __syncthreads();
        for (int q = tid; q < 4096; q += 256) {
            int c = q >> 4, t8 = (q & 15) * 8;
            uint4 vh = *(uint4*)(smem + c * 272 + t8 * 2);
            uint4 vl = *(uint4*)(smem + 69632 + c * 272 + t8 * 2);
            int gc = col0 + c;
            size_t t = (size_t)(gc >> 7) * 256 + ((row0 + t8) >> 5);
            size_t off = t * TILE_B + (size_t)(gc & 127) * 80 + (t8 & 31) * 2;
            *(uint4*)(g_Vtp + off)           = vh;
            *(uint4*)(g_Vtp + off + TILE_HI) = vl;
        }
    }
}

// ---------------------------------------------------------------------------
// Scores: P = exp(QK^T/sqrt(512)) unnormalized, diag=0; packed hi/lo; rowsum.
__global__ __launch_bounds__(256) void scores_k()
{
    GEMM_PROLOG;
    const int row0 = blockIdx.y * 128, col0 = blockIdx.x * 256;
    float* s_rsum = (float*)(smem + SM_RSUM);
    if (tid < 128) s_rsum[tid] = 0.0f;
    {
        PACKED_MAINLOOP(g_Qp, (row0 >> 7) * 16, g_Kp,
                        (col0 >> 7) * 16, (col0 >> 7) * 16 + 16, CDIM / 32);
    }

    const float scale = 0.044194173824159216f;  // 1/sqrt(512)
#pragma unroll
    for (int i = 0; i < 4; i++)
#pragma unroll
        for (int hb = 0; hb < 2; hb++) {
            int rloc = wm * 64 + i * 16 + (lane >> 2) + hb * 8;
            int grow = row0 + rloc;
            float part = 0.0f;
#pragma unroll
            for (int j = 0; j < 8; j++) {
                int gcol = col0 + wn * 64 + j * 8 + (lane & 3) * 2;
                float p0 = (grow == gcol)     ? 0.0f : __expf(acc[i][j][hb * 2]     * scale);
                float p1 = (grow == gcol + 1) ? 0.0f : __expf(acc[i][j][hb * 2 + 1] * scale);
                part += p0 + p1;
                bf16 h0, l0, h1, l1;
                split2(p0, h0, l0); split2(p1, h1, l1);
                size_t t = (size_t)(grow >> 7) * 256 + (gcol >> 5);
                size_t off = t * TILE_B + (size_t)(grow & 127) * 80 + (gcol & 31) * 2;
                *(uint32_t*)(g_Pp + off)           = packbf(h0, h1);
                *(uint32_t*)(g_Pp + off + TILE_HI) = packbf(l0, l1);
            }
            part += __shfl_xor_sync(0xFFFFFFFF, part, 1);
            part += __shfl_xor_sync(0xFFFFFFFF, part, 2);
            if ((lane & 3) == 0) atomicAdd(&s_rsum[rloc], part);
        }
    __syncthreads();
    if (tid < 128) atomicAdd(&g_rowsum[row0 + tid], s_rsum[tid]);
}

// ---------------------------------------------------------------------------
// AV: m_bar = (P_unnorm @ V) / rowsum.  Tile 128x256, K=8192.
__global__ __launch_bounds__(256) void av_k(float* __restrict__ m_out)
{
    GEMM_PROLOG;
    const int row0 = blockIdx.y * 128, col0 = blockIdx.x * 256;
    {
        PACKED_MAINLOOP(g_Pp, (row0 >> 7) * 256, g_Vtp,
                        (col0 >> 7) * 256, (col0 >> 7) * 256 + 256, NTOK / 32);
    }

#pragma unroll
    for (int i = 0; i < 4; i++)
#pragma unroll
        for (int hb = 0; hb < 2; hb++) {
            int grow = row0 + wm * 64 + i * 16 + (lane >> 2) + hb * 8;
            float inv = 1.0f / __ldg(&g_rowsum[grow]);
#pragma unroll
            for (int j = 0; j < 8; j++) {
                int gcol = col0 + wn * 64 + j * 8 + (lane & 3) * 2;
                float2 o;
                o.x = acc[i][j][hb * 2]     * inv;
                o.y = acc[i][j][hb * 2 + 1] * inv;
                *(float2*)(m_out + (size_t)grow * CDIM + gcol) = o;
            }
        }
}

// ---------------------------------------------------------------------------
// attn[i,j] = (Phi+Plo)/rowsum[i], packed P -> row-major fp32.
__global__ __launch_bounds__(256) void normalize_k(float* __restrict__ attn)
{
    int64_t q = (int64_t)blockIdx.x * 256 + threadIdx.x;
    int i = (int)(q >> 10);
    int w = (int)(q & 1023);
    int kc = w >> 2, cc8 = (w & 3) * 16;
    float inv = 1.0f / __ldg(&g_rowsum[i]);
    size_t t = (size_t)(i >> 7) * 256 + kc;
    size_t off = t * TILE_B + (size_t)(i & 127) * 80 + cc8;
    uint4 vh = *(const uint4*)(g_Pp + off);
    uint4 vl = *(const uint4*)(g_Pp + off + TILE_HI);
    uint32_t hs[4] = {vh.x, vh.y, vh.z, vh.w};
    uint32_t ls[4] = {vl.x, vl.y, vl.z, vl.w};
    float o[8];
#pragma unroll
    for (int k = 0; k < 4; k++) {
        __nv_bfloat162 h2 = *reinterpret_cast<__nv_bfloat162*>(&hs[k]);
        __nv_bfloat162 l2 = *reinterpret_cast<__nv_bfloat162*>(&ls[k]);
        float2 hf = __bfloat1622float2(h2);
        float2 lf = __bfloat1622float2(l2);
        o[2 * k]     = (hf.x + lf.x) * inv;
        o[2 * k + 1] = (hf.y + lf.y) * inv;
    }
    float* dst = attn + (size_t)i * NTOK + kc * 32 + (cc8 >> 1);
    *(float4*)(dst)     = make_float4(o[0], o[1], o[2], o[3]);
    *(float4*)(dst + 4) = make_float4(o[4], o[5], o[6], o[7]);
}

// ---------------------------------------------------------------------------
extern "C" void kernel_launch(void* const* d_in, const int* in_sizes, int n_in,
                              void* d_out, int out_size)
{
    (void)in_sizes; (void)n_in; (void)out_size;
    const float* u  = (const float*)d_in[0];
    const float* z  = (const float*)d_in[1];
    const float* Wk = (const float*)d_in[2];
    const float* bk = (const float*)d_in[3];
    const float* Wv = (const float*)d_in[4];
    const float* bv = (const float*)d_in[5];
    const float* Wq = (const float*)d_in[6];
    const float* bq = (const float*)d_in[7];

    float* m_out    = (float*)d_out;                  // (8192, 512)
    float* attn_out = m_out + (size_t)NTOK * CDIM;    // (8192, 8192)

    cudaFuncSetAttribute(proj_k,   cudaFuncAttributeMaxDynamicSharedMemorySize, SM_TOTAL);
    cudaFuncSetAttribute(scores_k, cudaFuncAttributeMaxDynamicSharedMemorySize, SM_TOTAL);
    cudaFuncSetAttribute(av_k,     cudaFuncAttributeMaxDynamicSharedMemorySize, SM_TOTAL);

    zero_rowsum_kernel<<<NTOK / 256, 256>>>();
    split_S_kernel<<<(NTOK * INDIM / 8) / 256, 256>>>(u, z);
    split_W_kernel<<<(CDIM * INDIM / 8) / 256, 256>>>(Wk, 0);
    split_W_kernel<<<(CDIM * INDIM / 8) / 256, 256>>>(Wv, 1);
    split_W_kernel<<<(CDIM * INDIM / 8) / 256, 256>>>(Wq, 2);

    dim3 pgrid(CDIM / 256, NTOK / 128);               // (2, 64)
    proj_k<<<pgrid, 256, SM_TOTAL>>>(bk, 0);
    proj_k<<<pgrid, 256, SM_TOTAL>>>(bv, 1);
    proj_k<<<pgrid, 256, SM_TOTAL>>>(bq, 2);

    dim3 sgrid(NTOK / 256, NTOK / 128);               // (32, 64)
    scores_k<<<sgrid, 256, SM_TOTAL>>>();

    dim3 agrid(CDIM / 256, NTOK / 128);               // (2, 64)
    av_k<<<agrid, 256, SM_TOTAL>>>(m_out);

    normalize_k<<<(unsigned)(((size_t)NTOK * NTOK / 8) / 256), 256>>>(attn_out);
}

// round 7
// speedup vs baseline: 1.1338x; 1.1338x over previous
#include <cuda_runtime.h>
#include <cuda_bf16.h>
#include <cstdint>

#define NTOK  8192
#define INDIM 1024
#define CDIM  512

using bf16 = __nv_bfloat16;

// Packed tile: 128 rows x 32 cols bf16, pitch 80 B; hi (10240 B) then lo. 20480 B.
#define TILE_B  20480
#define TILE_HI 10240

// ---------------------------------------------------------------------------
__device__ __align__(1024) char g_Sp[(size_t)2048 * TILE_B];    // S: [rb 64][kc 32]
__device__ __align__(1024) char g_Wp[3][(size_t)128 * TILE_B];  // W: [rb 4][kc 32]
__device__ __align__(1024) char g_Qp[(size_t)1024 * TILE_B];    // Q: [rb 64][kc 16]
__device__ __align__(1024) char g_Kp[(size_t)1024 * TILE_B];    // K: [rb 64][kc 16]
__device__ __align__(1024) char g_Vtp[(size_t)1024 * TILE_B];   // V^T: [rb 4][kc 256]
__device__ __align__(1024) char g_Pp[(size_t)16384 * TILE_B];   // P: [rb 64][kc 256]
__device__ float g_rowsum[NTOK];

// ---------------------------------------------------------------------------
__device__ __forceinline__ uint32_t su32(const void* p) {
    uint32_t a;
    asm("{ .reg .u64 t; cvta.to.shared.u64 t, %1; cvt.u32.u64 %0, t; }" : "=r"(a) : "l"(p));
    return a;
}
__device__ __forceinline__ void mbar_init(uint32_t m, uint32_t c) {
    asm volatile("mbarrier.init.shared.b64 [%0], %1;" :: "r"(m), "r"(c) : "memory");
}
__device__ __forceinline__ void mbar_expect(uint32_t m, uint32_t bytes) {
    asm volatile("mbarrier.arrive.expect_tx.shared.b64 _, [%0], %1;" :: "r"(m), "r"(bytes) : "memory");
}
__device__ __forceinline__ void mbar_arrive(uint32_t m) {
    asm volatile("mbarrier.arrive.release.cta.shared.b64 _, [%0];" :: "r"(m) : "memory");
}
__device__ __forceinline__ void mbar_wait(uint32_t m, uint32_t parity) {
    asm volatile(
        "{\n\t.reg .pred P1;\n\t"
        "WL_%=:\n\t"
        "mbarrier.try_wait.parity.acquire.cta.shared::cta.b64 P1, [%0], %1, 0x989680;\n\t"
        "@P1 bra.uni WD_%=;\n\t"
        "bra.uni WL_%=;\n\t"
        "WD_%=:\n\t}"
        :: "r"(m), "r"(parity) : "memory");
}
__device__ __forceinline__ void bulk_g2s(uint32_t sdst, const void* gsrc, uint32_t bytes, uint32_t mbar) {
    asm volatile(
        "cp.async.bulk.shared::cluster.global.mbarrier::complete_tx::bytes [%0], [%1], %2, [%3];"
        :: "r"(sdst), "l"(__cvta_generic_to_global(gsrc)), "r"(bytes), "r"(mbar) : "memory");
}
__device__ __forceinline__ void ldm4(uint32_t& r0, uint32_t& r1, uint32_t& r2, uint32_t& r3, uint32_t a) {
    asm volatile("ldmatrix.sync.aligned.m8n8.x4.shared.b16 {%0,%1,%2,%3}, [%4];"
                 : "=r"(r0), "=r"(r1), "=r"(r2), "=r"(r3) : "r"(a));
}
__device__ __forceinline__ void mma16816(float* c, const uint32_t* a, const uint32_t* b) {
    asm volatile(
        "mma.sync.aligned.m16n8k16.row.col.f32.bf16.bf16.f32 "
        "{%0,%1,%2,%3}, {%4,%5,%6,%7}, {%8,%9}, {%0,%1,%2,%3};"
        : "+f"(c[0]), "+f"(c[1]), "+f"(c[2]), "+f"(c[3])
        : "r"(a[0]), "r"(a[1]), "r"(a[2]), "r"(a[3]), "r"(b[0]), "r"(b[1]));
}
__device__ __forceinline__ void split2(float v, bf16& h, bf16& l) {
    h = __float2bfloat16(v);
    l = __float2bfloat16(v - __bfloat162float(h));
}
__device__ __forceinline__ uint32_t packbf(bf16 a, bf16 b) {
    return ((uint32_t)__bfloat16_as_ushort(b) << 16) | __bfloat16_as_ushort(a);
}

// ---------------------------------------------------------------------------
// SMEM: stage = [A_HI 10240][A_LO 10240][B_HI 10240][B_LO 10240] = 40960 B; x2 stages
#define A_HI   0
#define A_LO   10240
#define B_HI   20480
#define B_LO   30720
#define STAGE  40960
#define SM_RSUM 81920
#define SM_MBAR 82432            // full0, full1, empty0, empty1 (8 B each)
#define SM_TOTAL 82464

// Compute one 32-K chunk, 3 split combos, into acc[4][4][4]. (Unchanged from R5.)
__device__ __forceinline__ void compute_stage(uint32_t sb, int wm, int wn, int lane,
                                              float acc[4][4][4])
{
    const uint32_t a_off = (lane & 15) * 80 + (lane >> 4) * 16;
    const uint32_t b_off = ((lane & 7) + ((lane >> 4) & 1) * 8) * 80 + ((lane >> 3) & 1) * 16;
#pragma unroll
    for (int kk = 0; kk < 2; kk++) {
        uint32_t bh[8], bl[8], a[16];
#pragma unroll
        for (int jj = 0; jj < 2; jj++) {
            uint32_t ad = sb + B_HI + (wn * 32 + jj * 16) * 80 + kk * 32 + b_off;
            ldm4(bh[jj * 4], bh[jj * 4 + 1], bh[jj * 4 + 2], bh[jj * 4 + 3], ad);
            ldm4(bl[jj * 4], bl[jj * 4 + 1], bl[jj * 4 + 2], bl[jj * 4 + 3], ad + (B_LO - B_HI));
        }
#pragma unroll
        for (int i = 0; i < 4; i++) {
            uint32_t ad = sb + A_HI + (wm * 64 + i * 16) * 80 + kk * 32 + a_off;
            ldm4(a[i * 4], a[i * 4 + 1], a[i * 4 + 2], a[i * 4 + 3], ad);
        }
#pragma unroll
        for (int i = 0; i < 4; i++)
#pragma unroll
            for (int j = 0; j < 4; j++) {
                mma16816(acc[i][j], &a[i * 4], &bh[j * 2]);
                mma16816(acc[i][j], &a[i * 4], &bl[j * 2]);
            }
#pragma unroll
        for (int i = 0; i < 4; i++) {
            uint32_t ad = sb + A_LO + (wm * 64 + i * 16) * 80 + kk * 32 + a_off;
            ldm4(a[i * 4], a[i * 4 + 1], a[i * 4 + 2], a[i * 4 + 3], ad);
        }
#pragma unroll
        for (int i = 0; i < 4; i++)
#pragma unroll
            for (int j = 0; j < 4; j++)
                mma16816(acc[i][j], &a[i * 4], &bh[j * 2]);
    }
}

// Full/empty mbarrier pipeline, 2 stages. FULL: tx barrier (count 1).
// EMPTY: arrive-count 8 (one elect per warp). No block-wide syncs in loop.
#define FULLB(b)  (sb + SM_MBAR + (b) * 8)
#define EMPTYB(b) (sb + SM_MBAR + 16 + (b) * 8)

#define ISSUE_CHUNK(kc)                                                                      \
    do {                                                                                     \
        uint32_t s_ = sb + ((kc) & 1) * STAGE;                                               \
        uint32_t m_ = FULLB((kc) & 1);                                                       \
        mbar_expect(m_, 2 * TILE_B);                                                         \
        bulk_g2s(s_,        Abase + (size_t)(at0 + (kc)) * TILE_B, TILE_B, m_);              \
        bulk_g2s(s_ + B_HI, Bbase + (size_t)(bt0 + (kc)) * TILE_B, TILE_B, m_);              \
    } while (0)

#define PACKED_MAINLOOP(AbaseE, at0E, BbaseE, bt0E, NCH)                                     \
    const char* Abase = (AbaseE); const char* Bbase = (BbaseE);                              \
    const int at0 = (at0E), bt0 = (bt0E);                                                    \
    if (tid == 0) {                                                                          \
        mbar_init(FULLB(0), 1);  mbar_init(FULLB(1), 1);                                     \
        mbar_init(EMPTYB(0), 8); mbar_init(EMPTYB(1), 8);                                    \
    }                                                                                        \
    __syncthreads();                                                                         \
    if (tid == 0) { ISSUE_CHUNK(0); ISSUE_CHUNK(1); }                                        \
    for (int kc = 0; kc < (NCH); kc++) {                                                     \
        mbar_wait(FULLB(kc & 1), (uint32_t)((kc >> 1) & 1));                                 \
        compute_stage(sb + (kc & 1) * STAGE, wm, wn, lane, acc);                             \
        if (lane == 0) mbar_arrive(EMPTYB(kc & 1));                                          \
        if (tid == 0 && kc + 2 < (NCH)) {                                                    \
            mbar_wait(EMPTYB(kc & 1), (uint32_t)((kc >> 1) & 1));                            \
            ISSUE_CHUNK(kc + 2);                                                             \
        }                                                                                    \
    }                                                                                        \
    __syncthreads();

#define GEMM_PROLOG                                                   \
    extern __shared__ char smem[];                                    \
    const uint32_t sb = su32(smem);                                   \
    const int tid = threadIdx.x;                                      \
    const int lane = tid & 31, warp = tid >> 5;                       \
    const int wm = warp >> 2, wn = warp & 3;                          \
    float acc[4][4][4];                                               \
    _Pragma("unroll") for (int i = 0; i < 4; i++)                     \
    _Pragma("unroll") for (int j = 0; j < 4; j++)                     \
    _Pragma("unroll") for (int k = 0; k < 4; k++) acc[i][j][k] = 0.0f;

// ---------------------------------------------------------------------------
__global__ void zero_rowsum_kernel() {
    int i = blockIdx.x * blockDim.x + threadIdx.x;
    if (i < NTOK) g_rowsum[i] = 0.0f;
}

// split concat(u,z) fp32 -> packed hi/lo tiles in g_Sp
__global__ __launch_bounds__(256) void split_S_kernel(
    const float* __restrict__ u, const float* __restrict__ z)
{
    int idx = blockIdx.x * 256 + threadIdx.x;
    int row = idx >> 7;
    int c0 = (idx & 127) * 8;
    const float* src = (c0 < 512) ? (u + (size_t)row * 512 + c0)
                                  : (z + (size_t)row * 512 + c0 - 512);
    float4 a = *(const float4*)src;
    float4 b = *(const float4*)(src + 4);
    float x[8] = {a.x, a.y, a.z, a.w, b.x, b.y, b.z, b.w};
    uint32_t hw[4], lw[4];
#pragma unroll
    for (int i = 0; i < 4; i++) {
        bf16 h0, l0, h1, l1;
        split2(x[2 * i], h0, l0); split2(x[2 * i + 1], h1, l1);
        hw[i] = packbf(h0, h1); lw[i] = packbf(l0, l1);
    }
    size_t t = (size_t)(row >> 7) * 32 + (c0 >> 5);
    size_t off = t * TILE_B + (size_t)(row & 127) * 80 + (c0 & 31) * 2;
    *(uint4*)(g_Sp + off)           = make_uint4(hw[0], hw[1], hw[2], hw[3]);
    *(uint4*)(g_Sp + off + TILE_HI) = make_uint4(lw[0], lw[1], lw[2], lw[3]);
}

// split W[512][1024] -> packed tiles in g_Wp[sel]
__global__ __launch_bounds__(256) void split_W_kernel(const float* __restrict__ W, int sel)
{
    int idx = blockIdx.x * 256 + threadIdx.x;
    int row = idx >> 7;
    int c0 = (idx & 127) * 8;
    const float* src = W + (size_t)row * INDIM + c0;
    float4 a = *(const float4*)src;
    float4 b = *(const float4*)(src + 4);
    float x[8] = {a.x, a.y, a.z, a.w, b.x, b.y, b.z, b.w};
    uint32_t hw[4], lw[4];
#pragma unroll
    for (int i = 0; i < 4; i++) {
        bf16 h0, l0, h1, l1;
        split2(x[2 * i], h0, l0); split2(x[2 * i + 1], h1, l1);
        hw[i] = packbf(h0, h1); lw[i] = packbf(l0, l1);
    }
    size_t t = (size_t)(row >> 7) * 32 + (c0 >> 5);
    size_t off = t * TILE_B + (size_t)(row & 127) * 80 + (c0 & 31) * 2;
    *(uint4*)(g_Wp[sel] + off)           = make_uint4(hw[0], hw[1], hw[2], hw[3]);
    *(uint4*)(g_Wp[sel] + off + TILE_HI) = make_uint4(lw[0], lw[1], lw[2], lw[3]);
}

// ---------------------------------------------------------------------------
// Projection: tile 128x128, K=1024. sel: 0->K, 1->V(transposed), 2->Q
__global__ __launch_bounds__(256, 2) void proj_k(const float* __restrict__ bias, int sel)
{
    GEMM_PROLOG;
    const int row0 = blockIdx.y * 128, col0 = blockIdx.x * 128;
    {
        PACKED_MAINLOOP(g_Sp, (row0 >> 7) * 32, g_Wp[sel], (col0 >> 7) * 32, INDIM / 32);
    }

    if (sel != 1) {
        char* outp = (sel == 2) ? g_Qp : g_Kp;
#pragma unroll
        for (int i = 0; i < 4; i++)
#pragma unroll
            for (int hb = 0; hb < 2; hb++) {
                int grow = row0 + wm * 64 + i * 16 + (lane >> 2) + hb * 8;
#pragma unroll
                for (int j = 0; j < 4; j++) {
                    int gcol = col0 + wn * 32 + j * 8 + (lane & 3) * 2;
                    float v0 = acc[i][j][hb * 2]     + __ldg(bias + gcol);
                    float v1 = acc[i][j][hb * 2 + 1] + __ldg(bias + gcol + 1);
                    bf16 h0, l0, h1, l1;
                    split2(v0, h0, l0); split2(v1, h1, l1);
                    size_t t = (size_t)(grow >> 7) * 16 + (gcol >> 5);
                    size_t off = t * TILE_B + (size_t)(grow & 127) * 80 + (gcol & 31) * 2;
                    *(uint32_t*)(outp + off)           = packbf(h0, h1);
                    *(uint32_t*)(outp + off + TILE_HI) = packbf(l0, l1);
                }
            }
    } else {
        // V: transpose via smem then packed 16B stores into g_Vtp
        // hi plane at 0, lo plane at 34816; pitch 272 B; [c 128][tok 128].
#pragma unroll
        for (int i = 0; i < 4; i++)
#pragma unroll
            for (int hb = 0; hb < 2; hb++) {
                int tok = wm * 64 + i * 16 + (lane >> 2) + hb * 8;
#pragma unroll
                for (int j = 0; j < 4; j++) {
                    int cl = wn * 32 + j * 8 + (lane & 3) * 2;
                    float v0 = acc[i][j][hb * 2]     + __ldg(bias + col0 + cl);
                    float v1 = acc[i][j][hb * 2 + 1] + __ldg(bias + col0 + cl + 1);
                    bf16 h0, l0, h1, l1;
                    split2(v0, h0, l0); split2(v1, h1, l1);
                    *(bf16*)(smem + cl * 272 + tok * 2)               = h0;
                    *(bf16*)(smem + 34816 + cl * 272 + tok * 2)       = l0;
                    *(bf16*)(smem + (cl + 1) * 272 + tok * 2)         = h1;
                    *(bf16*)(smem + 34816 + (cl + 1) * 272 + tok * 2) = l1;
                }
            }
        __syncthreads();
        for (int q = tid; q < 2048; q += 256) {
            int c = q >> 4, t8 = (q & 15) * 8;
            uint4 vh = *(uint4*)(smem + c * 272 + t8 * 2);
            uint4 vl = *(uint4*)(smem + 34816 + c * 272 + t8 * 2);
            size_t t = (size_t)(col0 >> 7) * 256 + ((row0 + t8) >> 5);
            size_t off = t * TILE_B + (size_t)c * 80 + (t8 & 31) * 2;
            *(uint4*)(g_Vtp + off)           = vh;
            *(uint4*)(g_Vtp + off + TILE_HI) = vl;
        }
    }
}

// ---------------------------------------------------------------------------
// Scores: P = exp(QK^T/sqrt(512)) unnormalized, diag=0, packed hi/lo; rowsum.
__global__ __launch_bounds__(256, 2) void scores_k()
{
    GEMM_PROLOG;
    const int row0 = blockIdx.y * 128, col0 = blockIdx.x * 128;
    float* s_rsum = (float*)(smem + SM_RSUM);
    if (tid < 128) s_rsum[tid] = 0.0f;
    {
        PACKED_MAINLOOP(g_Qp, (row0 >> 7) * 16, g_Kp, (col0 >> 7) * 16, CDIM / 32);
    }

    const float scale = 0.044194173824159216f;  // 1/sqrt(512)
#pragma unroll
    for (int i = 0; i < 4; i++)
#pragma unroll
        for (int hb = 0; hb < 2; hb++) {
            int rloc = wm * 64 + i * 16 + (lane >> 2) + hb * 8;
            int grow = row0 + rloc;
            float part = 0.0f;
#pragma unroll
            for (int j = 0; j < 4; j++) {
                int gcol = col0 + wn * 32 + j * 8 + (lane & 3) * 2;
                float p0 = (grow == gcol)     ? 0.0f : __expf(acc[i][j][hb * 2]     * scale);
                float p1 = (grow == gcol + 1) ? 0.0f : __expf(acc[i][j][hb * 2 + 1] * scale);
                part += p0 + p1;
                bf16 h0, l0, h1, l1;
                split2(p0, h0, l0); split2(p1, h1, l1);
                size_t t = (size_t)(grow >> 7) * 256 + (gcol >> 5);
                size_t off = t * TILE_B + (size_t)(grow & 127) * 80 + (gcol & 31) * 2;
                *(uint32_t*)(g_Pp + off)           = packbf(h0, h1);
                *(uint32_t*)(g_Pp + off + TILE_HI) = packbf(l0, l1);
            }
            part += __shfl_xor_sync(0xFFFFFFFF, part, 1);
            part += __shfl_xor_sync(0xFFFFFFFF, part, 2);
            if ((lane & 3) == 0) atomicAdd(&s_rsum[rloc], part);
        }
    __syncthreads();
    if (tid < 128) atomicAdd(&g_rowsum[row0 + tid], s_rsum[tid]);
}

// ---------------------------------------------------------------------------
// AV: m_bar = (P_unnorm @ V) / rowsum.  Tile 128x128, K=8192.
__global__ __launch_bounds__(256, 2) void av_k(float* __restrict__ m_out)
{
    GEMM_PROLOG;
    const int row0 = blockIdx.y * 128, col0 = blockIdx.x * 128;
    {
        PACKED_MAINLOOP(g_Pp, (row0 >> 7) * 256, g_Vtp, (col0 >> 7) * 256, NTOK / 32);
    }

#pragma unroll
    for (int i = 0; i < 4; i++)
#pragma unroll
        for (int hb = 0; hb < 2; hb++) {
            int grow = row0 + wm * 64 + i * 16 + (lane >> 2) + hb * 8;
            float inv = 1.0f / __ldg(&g_rowsum[grow]);
#pragma unroll
            for (int j = 0; j < 4; j++) {
                int gcol = col0 + wn * 32 + j * 8 + (lane & 3) * 2;
                float2 o;
                o.x = acc[i][j][hb * 2]     * inv;
                o.y = acc[i][j][hb * 2 + 1] * inv;
                *(float2*)(m_out + (size_t)grow * CDIM + gcol) = o;
            }
        }
}

// ---------------------------------------------------------------------------
// attn[i,j] = (Phi+Plo)/rowsum[i], packed P -> row-major fp32.
__global__ __launch_bounds__(256) void normalize_k(float* __restrict__ attn)
{
    int64_t q = (int64_t)blockIdx.x * 256 + threadIdx.x;
    int i = (int)(q >> 10);
    int w = (int)(q & 1023);
    int kc = w >> 2, cc8 = (w & 3) * 16;
    float inv = 1.0f / __ldg(&g_rowsum[i]);
    size_t t = (size_t)(i >> 7) * 256 + kc;
    size_t off = t * TILE_B + (size_t)(i & 127) * 80 + cc8;
    uint4 vh = *(const uint4*)(g_Pp + off);
    uint4 vl = *(const uint4*)(g_Pp + off + TILE_HI);
    uint32_t hs[4] = {vh.x, vh.y, vh.z, vh.w};
    uint32_t ls[4] = {vl.x, vl.y, vl.z, vl.w};
    float o[8];
#pragma unroll
    for (int k = 0; k < 4; k++) {
        __nv_bfloat162 h2 = *reinterpret_cast<__nv_bfloat162*>(&hs[k]);
        __nv_bfloat162 l2 = *reinterpret_cast<__nv_bfloat162*>(&ls[k]);
        float2 hf = __bfloat1622float2(h2);
        float2 lf = __bfloat1622float2(l2);
        o[2 * k]     = (hf.x + lf.x) * inv;
        o[2 * k + 1] = (hf.y + lf.y) * inv;
    }
    float* dst = attn + (size_t)i * NTOK + kc * 32 + (cc8 >> 1);
    *(float4*)(dst)     = make_float4(o[0], o[1], o[2], o[3]);
    *(float4*)(dst + 4) = make_float4(o[4], o[5], o[6], o[7]);
}

// ---------------------------------------------------------------------------
extern "C" void kernel_launch(void* const* d_in, const int* in_sizes, int n_in,
                              void* d_out, int out_size)
{
    (void)in_sizes; (void)n_in; (void)out_size;
    const float* u  = (const float*)d_in[0];
    const float* z  = (const float*)d_in[1];
    const float* Wk = (const float*)d_in[2];
    const float* bk = (const float*)d_in[3];
    const float* Wv = (const float*)d_in[4];
    const float* bv = (const float*)d_in[5];
    const float* Wq = (const float*)d_in[6];
    const float* bq = (const float*)d_in[7];

    float* m_out    = (float*)d_out;                  // (8192, 512)
    float* attn_out = m_out + (size_t)NTOK * CDIM;    // (8192, 8192)

    cudaFuncSetAttribute(proj_k,   cudaFuncAttributeMaxDynamicSharedMemorySize, SM_TOTAL);
    cudaFuncSetAttribute(scores_k, cudaFuncAttributeMaxDynamicSharedMemorySize, SM_TOTAL);
    cudaFuncSetAttribute(av_k,     cudaFuncAttributeMaxDynamicSharedMemorySize, SM_TOTAL);

    zero_rowsum_kernel<<<NTOK / 256, 256>>>();
    split_S_kernel<<<(NTOK * INDIM / 8) / 256, 256>>>(u, z);
    split_W_kernel<<<(CDIM * INDIM / 8) / 256, 256>>>(Wk, 0);
    split_W_kernel<<<(CDIM * INDIM / 8) / 256, 256>>>(Wv, 1);
    split_W_kernel<<<(CDIM * INDIM / 8) / 256, 256>>>(Wq, 2);

    dim3 pgrid(CDIM / 128, NTOK / 128);               // (4, 64)
    proj_k<<<pgrid, 256, SM_TOTAL>>>(bk, 0);
    proj_k<<<pgrid, 256, SM_TOTAL>>>(bv, 1);
    proj_k<<<pgrid, 256, SM_TOTAL>>>(bq, 2);

    dim3 sgrid(NTOK / 128, NTOK / 128);               // (64, 64)
    scores_k<<<sgrid, 256, SM_TOTAL>>>();

    dim3 agrid(CDIM / 128, NTOK / 128);               // (4, 64)
    av_k<<<agrid, 256, SM_TOTAL>>>(m_out);

    normalize_k<<<(unsigned)(((size_t)NTOK * NTOK / 8) / 256), 256>>>(attn_out);
}

// round 8
// speedup vs baseline: 1.2078x; 1.0653x over previous
#include <cuda_runtime.h>
#include <cuda_bf16.h>
#include <cstdint>

#define NTOK  8192
#define INDIM 1024
#define CDIM  512

using bf16 = __nv_bfloat16;

// Packed tile: 128 rows x 32 cols bf16, pitch 80 B; hi (10240 B) then lo. 20480 B.
#define TILE_B  20480
#define TILE_HI 10240

// ---------------------------------------------------------------------------
__device__ __align__(1024) char g_Sp[(size_t)2048 * TILE_B];    // S: [rb 64][kc 32]
__device__ __align__(1024) char g_Wp[3][(size_t)128 * TILE_B];  // W: [rb 4][kc 32]
__device__ __align__(1024) char g_Qp[(size_t)1024 * TILE_B];    // Q: [rb 64][kc 16]
__device__ __align__(1024) char g_Kp[(size_t)1024 * TILE_B];    // K: [rb 64][kc 16]
__device__ __align__(1024) char g_Vtp[(size_t)1024 * TILE_B];   // V^T: [rb 4][kc 256]
__device__ __align__(1024) char g_Pp[(size_t)16384 * TILE_B];   // P: [rb 64][kc 256]
__device__ float g_rowsum[NTOK];

// ---------------------------------------------------------------------------
__device__ __forceinline__ uint32_t su32(const void* p) {
    uint32_t a;
    asm("{ .reg .u64 t; cvta.to.shared.u64 t, %1; cvt.u32.u64 %0, t; }" : "=r"(a) : "l"(p));
    return a;
}
__device__ __forceinline__ void mbar_init(uint32_t m, uint32_t c) {
    asm volatile("mbarrier.init.shared.b64 [%0], %1;" :: "r"(m), "r"(c) : "memory");
}
__device__ __forceinline__ void mbar_expect(uint32_t m, uint32_t bytes) {
    asm volatile("mbarrier.arrive.expect_tx.shared.b64 _, [%0], %1;" :: "r"(m), "r"(bytes) : "memory");
}
__device__ __forceinline__ void mbar_wait(uint32_t m, uint32_t parity) {
    asm volatile(
        "{\n\t.reg .pred P1;\n\t"
        "WL_%=:\n\t"
        "mbarrier.try_wait.parity.acquire.cta.shared::cta.b64 P1, [%0], %1, 0x989680;\n\t"
        "@P1 bra.uni WD_%=;\n\t"
        "bra.uni WL_%=;\n\t"
        "WD_%=:\n\t}"
        :: "r"(m), "r"(parity) : "memory");
}
__device__ __forceinline__ void bulk_g2s(uint32_t sdst, const void* gsrc, uint32_t bytes, uint32_t mbar) {
    asm volatile(
        "cp.async.bulk.shared::cluster.global.mbarrier::complete_tx::bytes [%0], [%1], %2, [%3];"
        :: "r"(sdst), "l"(__cvta_generic_to_global(gsrc)), "r"(bytes), "r"(mbar) : "memory");
}
__device__ __forceinline__ void ldm4(uint32_t& r0, uint32_t& r1, uint32_t& r2, uint32_t& r3, uint32_t a) {
    asm volatile("ldmatrix.sync.aligned.m8n8.x4.shared.b16 {%0,%1,%2,%3}, [%4];"
                 : "=r"(r0), "=r"(r1), "=r"(r2), "=r"(r3) : "r"(a));
}
__device__ __forceinline__ void mma16816(float* c, const uint32_t* a, const uint32_t* b) {
    asm volatile(
        "mma.sync.aligned.m16n8k16.row.col.f32.bf16.bf16.f32 "
        "{%0,%1,%2,%3}, {%4,%5,%6,%7}, {%8,%9}, {%0,%1,%2,%3};"
        : "+f"(c[0]), "+f"(c[1]), "+f"(c[2]), "+f"(c[3])
        : "r"(a[0]), "r"(a[1]), "r"(a[2]), "r"(a[3]), "r"(b[0]), "r"(b[1]));
}
__device__ __forceinline__ void split2(float v, bf16& h, bf16& l) {
    h = __float2bfloat16(v);
    l = __float2bfloat16(v - __bfloat162float(h));
}
__device__ __forceinline__ uint32_t packbf(bf16 a, bf16 b) {
    return ((uint32_t)__bfloat16_as_ushort(b) << 16) | __bfloat16_as_ushort(a);
}
__device__ __forceinline__ float2 bf2f(uint32_t w) {
    __nv_bfloat162 h2 = *reinterpret_cast<__nv_bfloat162*>(&w);
    return __bfloat1622float2(h2);
}

// ---------------------------------------------------------------------------
// SMEM: stage = [A_HI 10240][A_LO 10240][B_HI 10240][B_LO 10240] = 40960 B; x2 stages
#define A_HI   0
#define A_LO   10240
#define B_HI   20480
#define B_LO   30720
#define STAGE  40960
#define SM_RSUM 81920
#define SM_MBAR 82432
#define SM_TOTAL 82448

// Compute one 32-K chunk, 3 split combos, into acc[4][4][4].
__device__ __forceinline__ void compute_stage(uint32_t sb, int wm, int wn, int lane,
                                              float acc[4][4][4])
{
    const uint32_t a_off = (lane & 15) * 80 + (lane >> 4) * 16;
    const uint32_t b_off = ((lane & 7) + ((lane >> 4) & 1) * 8) * 80 + ((lane >> 3) & 1) * 16;
#pragma unroll
    for (int kk = 0; kk < 2; kk++) {
        uint32_t bh[8], bl[8], a[16];
#pragma unroll
        for (int jj = 0; jj < 2; jj++) {
            uint32_t ad = sb + B_HI + (wn * 32 + jj * 16) * 80 + kk * 32 + b_off;
            ldm4(bh[jj * 4], bh[jj * 4 + 1], bh[jj * 4 + 2], bh[jj * 4 + 3], ad);
            ldm4(bl[jj * 4], bl[jj * 4 + 1], bl[jj * 4 + 2], bl[jj * 4 + 3], ad + (B_LO - B_HI));
        }
#pragma unroll
        for (int i = 0; i < 4; i++) {
            uint32_t ad = sb + A_HI + (wm * 64 + i * 16) * 80 + kk * 32 + a_off;
            ldm4(a[i * 4], a[i * 4 + 1], a[i * 4 + 2], a[i * 4 + 3], ad);
        }
#pragma unroll
        for (int i = 0; i < 4; i++)
#pragma unroll
            for (int j = 0; j < 4; j++) {
                mma16816(acc[i][j], &a[i * 4], &bh[j * 2]);
                mma16816(acc[i][j], &a[i * 4], &bl[j * 2]);
            }
#pragma unroll
        for (int i = 0; i < 4; i++) {
            uint32_t ad = sb + A_LO + (wm * 64 + i * 16) * 80 + kk * 32 + a_off;
            ldm4(a[i * 4], a[i * 4 + 1], a[i * 4 + 2], a[i * 4 + 3], ad);
        }
#pragma unroll
        for (int i = 0; i < 4; i++)
#pragma unroll
            for (int j = 0; j < 4; j++)
                mma16816(acc[i][j], &a[i * 4], &bh[j * 2]);
    }
}

#define ISSUE_CHUNK(kc)                                                                      \
    do {                                                                                     \
        uint32_t s_ = sb + ((kc) & 1) * STAGE;                                               \
        uint32_t m_ = ((kc) & 1) ? mb1 : mb0;                                                \
        mbar_expect(m_, 2 * TILE_B);                                                         \
        bulk_g2s(s_,        Abase + (size_t)(at0 + (kc)) * TILE_B, TILE_B, m_);              \
        bulk_g2s(s_ + B_HI, Bbase + (size_t)(bt0 + (kc)) * TILE_B, TILE_B, m_);              \
    } while (0)

#define PACKED_MAINLOOP(AbaseE, at0E, BbaseE, bt0E, NCH)                                     \
    const char* Abase = (AbaseE); const char* Bbase = (BbaseE);                              \
    const int at0 = (at0E), bt0 = (bt0E);                                                    \
    if (tid == 0) { mbar_init(mb0, 1); mbar_init(mb1, 1); }                                  \
    __syncthreads();                                                                         \
    if (tid == 0) { ISSUE_CHUNK(0); ISSUE_CHUNK(1); }                                        \
    for (int kc = 0; kc < (NCH); kc++) {                                                     \
        mbar_wait((kc & 1) ? mb1 : mb0, (uint32_t)((kc >> 1) & 1));                          \
        compute_stage(sb + (kc & 1) * STAGE, wm, wn, lane, acc);                             \
        __syncthreads();                                                                     \
        if (tid == 0 && kc + 2 < (NCH)) ISSUE_CHUNK(kc + 2);                                 \
    }

#define GEMM_PROLOG                                                   \
    extern __shared__ char smem[];                                    \
    const uint32_t sb = su32(smem);                                   \
    const uint32_t mb0 = sb + SM_MBAR, mb1 = sb + SM_MBAR + 8;        \
    const int tid = threadIdx.x;                                      \
    const int lane = tid & 31, warp = tid >> 5;                       \
    const int wm = warp >> 2, wn = warp & 3;                          \
    float acc[4][4][4];                                               \
    _Pragma("unroll") for (int i = 0; i < 4; i++)                     \
    _Pragma("unroll") for (int j = 0; j < 4; j++)                     \
    _Pragma("unroll") for (int k = 0; k < 4; k++) acc[i][j][k] = 0.0f;

// ---------------------------------------------------------------------------
__global__ void zero_rowsum_kernel() {
    int i = blockIdx.x * blockDim.x + threadIdx.x;
    if (i < NTOK) g_rowsum[i] = 0.0f;
}

__global__ __launch_bounds__(256) void split_S_kernel(
    const float* __restrict__ u, const float* __restrict__ z)
{
    int idx = blockIdx.x * 256 + threadIdx.x;
    int row = idx >> 7;
    int c0 = (idx & 127) * 8;
    const float* src = (c0 < 512) ? (u + (size_t)row * 512 + c0)
                                  : (z + (size_t)row * 512 + c0 - 512);
    float4 a = *(const float4*)src;
    float4 b = *(const float4*)(src + 4);
    float x[8] = {a.x, a.y, a.z, a.w, b.x, b.y, b.z, b.w};
    uint32_t hw[4], lw[4];
#pragma unroll
    for (int i = 0; i < 4; i++) {
        bf16 h0, l0, h1, l1;
        split2(x[2 * i], h0, l0); split2(x[2 * i + 1], h1, l1);
        hw[i] = packbf(h0, h1); lw[i] = packbf(l0, l1);
    }
    size_t t = (size_t)(row >> 7) * 32 + (c0 >> 5);
    size_t off = t * TILE_B + (size_t)(row & 127) * 80 + (c0 & 31) * 2;
    *(uint4*)(g_Sp + off)           = make_uint4(hw[0], hw[1], hw[2], hw[3]);
    *(uint4*)(g_Sp + off + TILE_HI) = make_uint4(lw[0], lw[1], lw[2], lw[3]);
}

// split all three W matrices in one launch: sel = blockIdx.y
__global__ __launch_bounds__(256) void split_W_kernel(
    const float* __restrict__ Wk, const float* __restrict__ Wv, const float* __restrict__ Wq)
{
    int sel = blockIdx.y;
    const float* W = (sel == 0) ? Wk : (sel == 1) ? Wv : Wq;
    int idx = blockIdx.x * 256 + threadIdx.x;
    int row = idx >> 7;
    int c0 = (idx & 127) * 8;
    const float* src = W + (size_t)row * INDIM + c0;
    float4 a = *(const float4*)src;
    float4 b = *(const float4*)(src + 4);
    float x[8] = {a.x, a.y, a.z, a.w, b.x, b.y, b.z, b.w};
    uint32_t hw[4], lw[4];
#pragma unroll
    for (int i = 0; i < 4; i++) {
        bf16 h0, l0, h1, l1;
        split2(x[2 * i], h0, l0); split2(x[2 * i + 1], h1, l1);
        hw[i] = packbf(h0, h1); lw[i] = packbf(l0, l1);
    }
    size_t t = (size_t)(row >> 7) * 32 + (c0 >> 5);
    size_t off = t * TILE_B + (size_t)(row & 127) * 80 + (c0 & 31) * 2;
    *(uint4*)(g_Wp[sel] + off)           = make_uint4(hw[0], hw[1], hw[2], hw[3]);
    *(uint4*)(g_Wp[sel] + off + TILE_HI) = make_uint4(lw[0], lw[1], lw[2], lw[3]);
}

// ---------------------------------------------------------------------------
// Projection (all three in one launch): tile 128x128, K=1024.
// blockIdx.z: 0->K, 1->V(transposed), 2->Q
__global__ __launch_bounds__(256, 2) void proj_k(
    const float* __restrict__ bk, const float* __restrict__ bv, const float* __restrict__ bq)
{
    GEMM_PROLOG;
    const int sel = blockIdx.z;
    const float* bias = (sel == 0) ? bk : (sel == 1) ? bv : bq;
    const int row0 = blockIdx.y * 128, col0 = blockIdx.x * 128;
    {
        PACKED_MAINLOOP(g_Sp, (row0 >> 7) * 32, g_Wp[sel], (col0 >> 7) * 32, INDIM / 32);
    }

    if (sel != 1) {
        char* outp = (sel == 2) ? g_Qp : g_Kp;
#pragma unroll
        for (int i = 0; i < 4; i++)
#pragma unroll
            for (int hb = 0; hb < 2; hb++) {
                int grow = row0 + wm * 64 + i * 16 + (lane >> 2) + hb * 8;
#pragma unroll
                for (int j = 0; j < 4; j++) {
                    int gcol = col0 + wn * 32 + j * 8 + (lane & 3) * 2;
                    float v0 = acc[i][j][hb * 2]     + __ldg(bias + gcol);
                    float v1 = acc[i][j][hb * 2 + 1] + __ldg(bias + gcol + 1);
                    bf16 h0, l0, h1, l1;
                    split2(v0, h0, l0); split2(v1, h1, l1);
                    size_t t = (size_t)(grow >> 7) * 16 + (gcol >> 5);
                    size_t off = t * TILE_B + (size_t)(grow & 127) * 80 + (gcol & 31) * 2;
                    *(uint32_t*)(outp + off)           = packbf(h0, h1);
                    *(uint32_t*)(outp + off + TILE_HI) = packbf(l0, l1);
                }
            }
    } else {
        // V: transpose via smem then packed 16B stores into g_Vtp
        // hi plane at 0, lo plane at 34816; pitch 272 B; [c 128][tok 128].
#pragma unroll
        for (int i = 0; i < 4; i++)
#pragma unroll
            for (int hb = 0; hb < 2; hb++) {
                int tok = wm * 64 + i * 16 + (lane >> 2) + hb * 8;
#pragma unroll
                for (int j = 0; j < 4; j++) {
                    int cl = wn * 32 + j * 8 + (lane & 3) * 2;
                    float v0 = acc[i][j][hb * 2]     + __ldg(bias + col0 + cl);
                    float v1 = acc[i][j][hb * 2 + 1] + __ldg(bias + col0 + cl + 1);
                    bf16 h0, l0, h1, l1;
                    split2(v0, h0, l0); split2(v1, h1, l1);
                    *(bf16*)(smem + cl * 272 + tok * 2)               = h0;
                    *(bf16*)(smem + 34816 + cl * 272 + tok * 2)       = l0;
                    *(bf16*)(smem + (cl + 1) * 272 + tok * 2)         = h1;
                    *(bf16*)(smem + 34816 + (cl + 1) * 272 + tok * 2) = l1;
                }
            }
        __syncthreads();
        for (int q = tid; q < 2048; q += 256) {
            int c = q >> 4, t8 = (q & 15) * 8;
            uint4 vh = *(uint4*)(smem + c * 272 + t8 * 2);
            uint4 vl = *(uint4*)(smem + 34816 + c * 272 + t8 * 2);
            size_t t = (size_t)(col0 >> 7) * 256 + ((row0 + t8) >> 5);
            size_t off = t * TILE_B + (size_t)c * 80 + (t8 & 31) * 2;
            *(uint4*)(g_Vtp + off)           = vh;
            *(uint4*)(g_Vtp + off + TILE_HI) = vl;
        }
    }
}

// ---------------------------------------------------------------------------
// Scores: P = exp(QK^T/sqrt(512)) unnormalized, diag=0, packed hi/lo; rowsum.
__global__ __launch_bounds__(256, 2) void scores_k()
{
    GEMM_PROLOG;
    const int row0 = blockIdx.y * 128, col0 = blockIdx.x * 128;
    float* s_rsum = (float*)(smem + SM_RSUM);
    if (tid < 128) s_rsum[tid] = 0.0f;
    {
        PACKED_MAINLOOP(g_Qp, (row0 >> 7) * 16, g_Kp, (col0 >> 7) * 16, CDIM / 32);
    }

    const float scale = 0.044194173824159216f;  // 1/sqrt(512)
#pragma unroll
    for (int i = 0; i < 4; i++)
#pragma unroll
        for (int hb = 0; hb < 2; hb++) {
            int rloc = wm * 64 + i * 16 + (lane >> 2) + hb * 8;
            int grow = row0 + rloc;
            float part = 0.0f;
#pragma unroll
            for (int j = 0; j < 4; j++) {
                int gcol = col0 + wn * 32 + j * 8 + (lane & 3) * 2;
                float p0 = (grow == gcol)     ? 0.0f : __expf(acc[i][j][hb * 2]     * scale);
                float p1 = (grow == gcol + 1) ? 0.0f : __expf(acc[i][j][hb * 2 + 1] * scale);
                part += p0 + p1;
                bf16 h0, l0, h1, l1;
                split2(p0, h0, l0); split2(p1, h1, l1);
                size_t t = (size_t)(grow >> 7) * 256 + (gcol >> 5);
                size_t off = t * TILE_B + (size_t)(grow & 127) * 80 + (gcol & 31) * 2;
                *(uint32_t*)(g_Pp + off)           = packbf(h0, h1);
                *(uint32_t*)(g_Pp + off + TILE_HI) = packbf(l0, l1);
            }
            part += __shfl_xor_sync(0xFFFFFFFF, part, 1);
            part += __shfl_xor_sync(0xFFFFFFFF, part, 2);
            if ((lane & 3) == 0) atomicAdd(&s_rsum[rloc], part);
        }
    __syncthreads();
    if (tid < 128) atomicAdd(&g_rowsum[row0 + tid], s_rsum[tid]);
}

// ---------------------------------------------------------------------------
// AV: m_bar = (P_unnorm @ V) / rowsum, tile 128x128, K=8192.
// FUSED: each CTA also converts its quarter of the P row-block (chunks with
// kc>>6 == blockIdx.x) from smem to normalized fp32 attn — deletes normalize_k.
__global__ __launch_bounds__(256, 2) void av_k(float* __restrict__ m_out,
                                               float* __restrict__ attn)
{
    GEMM_PROLOG;
    const int row0 = blockIdx.y * 128, col0 = blockIdx.x * 128;
    const int cvt_sel = blockIdx.x;          // which 64 chunks this CTA converts
    const int crow = tid >> 1;               // conversion row 0..127
    const int cseg = (tid & 1) * 16;         // conversion col segment 0 or 16
    const float cinv = 1.0f / g_rowsum[row0 + crow];

    const char* Abase = g_Pp;  const char* Bbase = g_Vtp;
    const int at0 = (row0 >> 7) * 256, bt0 = (col0 >> 7) * 256;
    if (tid == 0) { mbar_init(mb0, 1); mbar_init(mb1, 1); }
    __syncthreads();
    if (tid == 0) { ISSUE_CHUNK(0); ISSUE_CHUNK(1); }
    for (int kc = 0; kc < NTOK / 32; kc++) {
        mbar_wait((kc & 1) ? mb1 : mb0, (uint32_t)((kc >> 1) & 1));
        compute_stage(sb + (kc & 1) * STAGE, wm, wn, lane, acc);
        if ((kc >> 6) == cvt_sel) {
            // convert 16 elements: P[row0+crow][kc*32+cseg .. +16) -> attn fp32
            uint32_t soff = (kc & 1) * STAGE + (uint32_t)crow * 80 + cseg * 2;
            uint4 h0 = *(uint4*)(smem + soff);
            uint4 h1 = *(uint4*)(smem + soff + 16);
            uint4 l0 = *(uint4*)(smem + soff + TILE_HI);
            uint4 l1 = *(uint4*)(smem + soff + TILE_HI + 16);
            uint32_t hw[8] = {h0.x, h0.y, h0.z, h0.w, h1.x, h1.y, h1.z, h1.w};
            uint32_t lw[8] = {l0.x, l0.y, l0.z, l0.w, l1.x, l1.y, l1.z, l1.w};
            float o[16];
#pragma unroll
            for (int k = 0; k < 8; k++) {
                float2 hf = bf2f(hw[k]);
                float2 lf = bf2f(lw[k]);
                o[2 * k]     = (hf.x + lf.x) * cinv;
                o[2 * k + 1] = (hf.y + lf.y) * cinv;
            }
            float* dst = attn + (size_t)(row0 + crow) * NTOK + kc * 32 + cseg;
            *(float4*)(dst)      = make_float4(o[0],  o[1],  o[2],  o[3]);
            *(float4*)(dst + 4)  = make_float4(o[4],  o[5],  o[6],  o[7]);
            *(float4*)(dst + 8)  = make_float4(o[8],  o[9],  o[10], o[11]);
            *(float4*)(dst + 12) = make_float4(o[12], o[13], o[14], o[15]);
        }
        __syncthreads();
        if (tid == 0 && kc + 2 < NTOK / 32) ISSUE_CHUNK(kc + 2);
    }

#pragma unroll
    for (int i = 0; i < 4; i++)
#pragma unroll
        for (int hb = 0; hb < 2; hb++) {
            int grow = row0 + wm * 64 + i * 16 + (lane >> 2) + hb * 8;
            float inv = 1.0f / __ldg(&g_rowsum[grow]);
#pragma unroll
            for (int j = 0; j < 4; j++) {
                int gcol = col0 + wn * 32 + j * 8 + (lane & 3) * 2;
                float2 o;
                o.x = acc[i][j][hb * 2]     * inv;
                o.y = acc[i][j][hb * 2 + 1] * inv;
                *(float2*)(m_out + (size_t)grow * CDIM + gcol) = o;
            }
        }
}

// ---------------------------------------------------------------------------
extern "C" void kernel_launch(void* const* d_in, const int* in_sizes, int n_in,
                              void* d_out, int out_size)
{
    (void)in_sizes; (void)n_in; (void)out_size;
    const float* u  = (const float*)d_in[0];
    const float* z  = (const float*)d_in[1];
    const float* Wk = (const float*)d_in[2];
    const float* bk = (const float*)d_in[3];
    const float* Wv = (const float*)d_in[4];
    const float* bv = (const float*)d_in[5];
    const float* Wq = (const float*)d_in[6];
    const float* bq = (const float*)d_in[7];

    float* m_out    = (float*)d_out;                  // (8192, 512)
    float* attn_out = m_out + (size_t)NTOK * CDIM;    // (8192, 8192)

    cudaFuncSetAttribute(proj_k,   cudaFuncAttributeMaxDynamicSharedMemorySize, SM_TOTAL);
    cudaFuncSetAttribute(scores_k, cudaFuncAttributeMaxDynamicSharedMemorySize, SM_TOTAL);
    cudaFuncSetAttribute(av_k,     cudaFuncAttributeMaxDynamicSharedMemorySize, SM_TOTAL);

    zero_rowsum_kernel<<<NTOK / 256, 256>>>();
    split_S_kernel<<<(NTOK * INDIM / 8) / 256, 256>>>(u, z);
    {
        dim3 wgrid((CDIM * INDIM / 8) / 256, 3);
        split_W_kernel<<<wgrid, 256>>>(Wk, Wv, Wq);
    }

    dim3 pgrid(CDIM / 128, NTOK / 128, 3);            // (4, 64, 3)
    proj_k<<<pgrid, 256, SM_TOTAL>>>(bk, bv, bq);

    dim3 sgrid(NTOK / 128, NTOK / 128);               // (64, 64)
    scores_k<<<sgrid, 256, SM_TOTAL>>>();

    dim3 agrid(CDIM / 128, NTOK / 128);               // (4, 64)
    av_k<<<agrid, 256, SM_TOTAL>>>(m_out, attn_out);
}